// round 11
// baseline (speedup 1.0000x reference)
#include <cuda_runtime.h>
#include <cuda_fp16.h>
#include <math.h>

#define N_NODES 50000
#define DIM 64
#define ROWS_PB 80        // rows per GEMM block (625 blocks exactly)
#define RPT 5             // rows per thread
#define CAP 96            // max in-degree capacity (Poisson(16) max ~45; safe)

// Scratch (allocation-free rule: __device__ globals)
__device__ __half2 g_h[N_NODES * DIM / 2];   // h = in @ W, fp16 for gather bandwidth
__device__ float   g_agg[N_NODES * DIM];     // inter-layer activation (fp32)
__device__ float   g_dinv[N_NODES];
__device__ int     g_cursor[N_NODES];        // degree counter / fill cursor
__device__ int     g_slot[N_NODES * CAP];    // bucketed src lists
__device__ int     g_is64;                   // edge_index dtype flag

// ---------------- f32x2 packed-FMA helpers ----------------
__device__ __forceinline__ unsigned long long pack2(float x, float y) {
    unsigned long long r;
    asm("mov.b64 %0, {%1, %2};" : "=l"(r) : "f"(x), "f"(y));
    return r;
}
__device__ __forceinline__ float2 unpack2(unsigned long long v) {
    float2 r;
    asm("mov.b64 {%0, %1}, %2;" : "=f"(r.x), "=f"(r.y) : "l"(v));
    return r;
}
__device__ __forceinline__ void ffma2(unsigned long long& acc,
                                      unsigned long long a, unsigned long long b) {
    asm("fma.rn.f32x2 %0, %1, %2, %0;" : "+l"(acc) : "l"(a), "l"(b));
}

// ---------------- dtype detect + zero cursors ----------------
__global__ void prep_kernel(const unsigned int* __restrict__ w) {
    int i = blockIdx.x * blockDim.x + threadIdx.x;
    if (i < N_NODES) g_cursor[i] = 0;
    if (i == 0) {
        int is64 = 1;
        for (int k = 0; k < 64; k++)
            if (w[2 * k + 1] != 0u) { is64 = 0; break; }
        g_is64 = is64;
    }
}

__device__ __forceinline__ int edge_src(const void* ei, int E, int e) {
    return g_is64 ? (int)((const long long*)ei)[e] : ((const int*)ei)[e];
}
__device__ __forceinline__ int edge_dst(const void* ei, int E, int e) {
    return g_is64 ? (int)((const long long*)ei)[E + e] : ((const int*)ei)[E + e];
}

// ---------------- bucket fill (single edge sweep; atomic = reservation + count) ----------------
__global__ void fill_kernel(const void* __restrict__ ei, int E) {
    int e = blockIdx.x * blockDim.x + threadIdx.x;
    if (e >= E) return;
    int s = edge_src(ei, E, e);
    int d = edge_dst(ei, E, e);
    int pos = atomicAdd(&g_cursor[d], 1);
    if (pos < CAP) g_slot[d * CAP + pos] = s;
}

// ---------------- dinv from final counts ----------------
__global__ void dinv_kernel() {
    int i = blockIdx.x * blockDim.x + threadIdx.x;
    if (i < N_NODES) g_dinv[i] = rsqrtf((float)(1 + g_cursor[i]));  // +1 self loop
}

// ---------------- GEMM: h = relu?(in) @ W  (5 rows/thread, FFMA2, k-pairs, fp16 out) ----------------
// 256 threads = 16 row-groups (5 rows each) x 16 col-groups (4 cols each).
template <bool RELU_IN>
__global__ void __launch_bounds__(256) gemm_kernel(
    const float* __restrict__ in, const float* __restrict__ W,
    __half2* __restrict__ h)
{
    __shared__ float4 Ws[DIM * 16];          // 16KB: W[k][c4] as float4
    __shared__ float  xs[ROWS_PB * DIM];     // 20KB: input tile

    const int tid  = threadIdx.x;
    const int row0 = blockIdx.x * ROWS_PB;

    // Load W (1024 float4) — 4 per thread
    const float4* Wg = (const float4*)W;
    #pragma unroll
    for (int i = 0; i < 4; i++)
        Ws[tid + i * 256] = Wg[tid + i * 256];

    // Load input tile (1280 float4) — 5 per thread, optional ReLU
    #pragma unroll
    for (int j = 0; j < 5; j++) {
        float4 v = ((const float4*)(in + row0 * DIM))[tid + j * 256];
        if (RELU_IN) {
            v.x = fmaxf(v.x, 0.0f); v.y = fmaxf(v.y, 0.0f);
            v.z = fmaxf(v.z, 0.0f); v.w = fmaxf(v.w, 0.0f);
        }
        ((float4*)xs)[tid + j * 256] = v;
    }
    __syncthreads();

    const int rg = tid >> 4;          // row group 0..15
    const int c4 = tid & 15;          // col group 0..15
    const int r0 = rg * RPT;          // first local row

    unsigned long long a01[RPT], a23[RPT];
    #pragma unroll
    for (int j = 0; j < RPT; j++) { a01[j] = 0ull; a23[j] = 0ull; }

    #pragma unroll 4
    for (int k = 0; k < DIM; k += 2) {
        float4 w0 = Ws[k * 16 + c4];
        float4 w1 = Ws[(k + 1) * 16 + c4];
        unsigned long long w0a = pack2(w0.x, w0.y);
        unsigned long long w0b = pack2(w0.z, w0.w);
        unsigned long long w1a = pack2(w1.x, w1.y);
        unsigned long long w1b = pack2(w1.z, w1.w);
        #pragma unroll
        for (int j = 0; j < RPT; j++) {
            float2 xv = *(const float2*)&xs[(r0 + j) * DIM + k];   // LDS.64, two k
            unsigned long long xp0 = pack2(xv.x, xv.x);
            unsigned long long xp1 = pack2(xv.y, xv.y);
            ffma2(a01[j], xp0, w0a);
            ffma2(a23[j], xp0, w0b);
            ffma2(a01[j], xp1, w1a);
            ffma2(a23[j], xp1, w1b);
        }
    }

    // Epilogue: convert 4 fp32 cols -> 2 half2, store 8B per thread
    #pragma unroll
    for (int j = 0; j < RPT; j++) {
        float2 lo = unpack2(a01[j]);
        float2 hi = unpack2(a23[j]);
        __half2 h0 = __floats2half2_rn(lo.x, lo.y);
        __half2 h1 = __floats2half2_rn(hi.x, hi.y);
        unsigned int u0 = *(unsigned int*)&h0;
        unsigned int u1 = *(unsigned int*)&h1;
        ((uint2*)(h + (row0 + r0 + j) * 32))[c4] = make_uint2(u0, u1);
    }
}

// ---------------- bucket gather: out[d] = b + h[d]*dinv[d]^2 + sum_in h[s]*dinv[d]*dinv[s] ----------------
// One warp per destination node; each lane owns 2 columns (one half2); 8-deep batch, 4 accumulators.
__global__ void __launch_bounds__(256) gather_kernel(
    const __half2* __restrict__ hp, const float* __restrict__ b,
    float* __restrict__ out)
{
    int node = blockIdx.x * 8 + (threadIdx.x >> 5);
    int lane = threadIdx.x & 31;
    if (node >= N_NODES) return;

    const int* slots = g_slot + node * CAP;
    int cnt = g_cursor[node];

    float2 hv = __half22float2(hp[node * 32 + lane]);
    float  did = g_dinv[node];
    float2 bv = ((const float2*)b)[lane];

    float2 a0, a1, a2, a3;
    float di2 = did * did;
    a0.x = fmaf(hv.x, di2, bv.x);
    a0.y = fmaf(hv.y, di2, bv.y);
    a1 = make_float2(0.f, 0.f);
    a2 = make_float2(0.f, 0.f);
    a3 = make_float2(0.f, 0.f);

    int i = 0;
    for (; i + 7 < cnt; i += 8) {
        int s0 = slots[i];     int s1 = slots[i + 1];
        int s2 = slots[i + 2]; int s3 = slots[i + 3];
        int s4 = slots[i + 4]; int s5 = slots[i + 5];
        int s6 = slots[i + 6]; int s7 = slots[i + 7];
        float n0 = g_dinv[s0], n1 = g_dinv[s1], n2 = g_dinv[s2], n3 = g_dinv[s3];
        float n4 = g_dinv[s4], n5 = g_dinv[s5], n6 = g_dinv[s6], n7 = g_dinv[s7];
        float2 v0 = __half22float2(hp[s0 * 32 + lane]);
        float2 v1 = __half22float2(hp[s1 * 32 + lane]);
        float2 v2 = __half22float2(hp[s2 * 32 + lane]);
        float2 v3 = __half22float2(hp[s3 * 32 + lane]);
        float2 v4 = __half22float2(hp[s4 * 32 + lane]);
        float2 v5 = __half22float2(hp[s5 * 32 + lane]);
        float2 v6 = __half22float2(hp[s6 * 32 + lane]);
        float2 v7 = __half22float2(hp[s7 * 32 + lane]);
        n0 *= did; n1 *= did; n2 *= did; n3 *= did;
        n4 *= did; n5 *= did; n6 *= did; n7 *= did;
        a0.x = fmaf(v0.x, n0, a0.x); a0.y = fmaf(v0.y, n0, a0.y);
        a1.x = fmaf(v1.x, n1, a1.x); a1.y = fmaf(v1.y, n1, a1.y);
        a2.x = fmaf(v2.x, n2, a2.x); a2.y = fmaf(v2.y, n2, a2.y);
        a3.x = fmaf(v3.x, n3, a3.x); a3.y = fmaf(v3.y, n3, a3.y);
        a0.x = fmaf(v4.x, n4, a0.x); a0.y = fmaf(v4.y, n4, a0.y);
        a1.x = fmaf(v5.x, n5, a1.x); a1.y = fmaf(v5.y, n5, a1.y);
        a2.x = fmaf(v6.x, n6, a2.x); a2.y = fmaf(v6.y, n6, a2.y);
        a3.x = fmaf(v7.x, n7, a3.x); a3.y = fmaf(v7.y, n7, a3.y);
    }
    for (; i < cnt; i++) {
        int s0 = slots[i];
        float n0 = g_dinv[s0] * did;
        float2 v0 = __half22float2(hp[s0 * 32 + lane]);
        a0.x = fmaf(v0.x, n0, a0.x);
        a0.y = fmaf(v0.y, n0, a0.y);
    }

    float2 r;
    r.x = (a0.x + a1.x) + (a2.x + a3.x);
    r.y = (a0.y + a1.y) + (a2.y + a3.y);
    ((float2*)out)[node * 32 + lane] = r;
}

// ---------------- launch ----------------
extern "C" void kernel_launch(void* const* d_in, const int* in_sizes, int n_in,
                              void* d_out, int out_size)
{
    const float* x  = (const float*)d_in[0];
    const void*  ei = d_in[1];
    const float* W0 = (const float*)d_in[2];
    const float* b0 = (const float*)d_in[3];
    const float* W1 = (const float*)d_in[4];
    const float* b1 = (const float*)d_in[5];
    const float* W2 = (const float*)d_in[6];
    const float* b2 = (const float*)d_in[7];
    float* out = (float*)d_out;

    const int E = in_sizes[1] / 2;

    __half2* p_h;
    float*   p_agg;
    cudaGetSymbolAddress((void**)&p_h,   g_h);
    cudaGetSymbolAddress((void**)&p_agg, g_agg);

    const int nodeBlocks = (N_NODES + 255) / 256;
    const int edgeBlocks = (E + 255) / 256;
    const int gemmBlocks = N_NODES / ROWS_PB;          // 625
    const int gathBlocks = (N_NODES + 7) / 8;          // 6250

    // bucket-CSR build (single edge sweep), single stream
    prep_kernel<<<nodeBlocks, 256>>>((const unsigned int*)ei);
    fill_kernel<<<edgeBlocks, 256>>>(ei, E);
    dinv_kernel<<<nodeBlocks, 256>>>();

    // layer 1
    gemm_kernel<false><<<gemmBlocks, 256>>>(x, W0, p_h);
    gather_kernel<<<gathBlocks, 256>>>(p_h, b0, p_agg);

    // layer 2
    gemm_kernel<true><<<gemmBlocks, 256>>>(p_agg, W1, p_h);
    gather_kernel<<<gathBlocks, 256>>>(p_h, b1, p_agg);

    // layer 3 -> d_out
    gemm_kernel<true><<<gemmBlocks, 256>>>(p_agg, W2, p_h);
    gather_kernel<<<gathBlocks, 256>>>(p_h, b2, out);
}

// round 13
// speedup vs baseline: 1.2296x; 1.2296x over previous
#include <cuda_runtime.h>
#include <cuda_fp16.h>
#include <math.h>

#define N_NODES 50000
#define DIM 64
#define ROWS_PB 80        // rows per GEMM block (625 blocks exactly)
#define RPT 5             // rows per thread
#define CAP 96            // max in-degree capacity (Poisson(16) max ~45; safe)

// Scratch (allocation-free rule: __device__ globals)
__device__ __half2 g_hs[N_NODES * DIM / 2];  // hs = (in @ W) * dinv[row], fp16
__device__ float   g_agg[N_NODES * DIM];     // inter-layer activation (fp32)
__device__ float   g_dinv[N_NODES];
__device__ int     g_cursor[N_NODES];        // degree counter / fill cursor
__device__ int     g_slot[N_NODES * CAP];    // bucketed src lists
__device__ int     g_is64;                   // edge_index dtype flag

// ---------------- f32x2 packed-FMA helpers ----------------
__device__ __forceinline__ unsigned long long pack2(float x, float y) {
    unsigned long long r;
    asm("mov.b64 %0, {%1, %2};" : "=l"(r) : "f"(x), "f"(y));
    return r;
}
__device__ __forceinline__ float2 unpack2(unsigned long long v) {
    float2 r;
    asm("mov.b64 {%0, %1}, %2;" : "=f"(r.x), "=f"(r.y) : "l"(v));
    return r;
}
__device__ __forceinline__ void ffma2(unsigned long long& acc,
                                      unsigned long long a, unsigned long long b) {
    asm("fma.rn.f32x2 %0, %1, %2, %0;" : "+l"(acc) : "l"(a), "l"(b));
}

// ---------------- dtype detect + zero cursors ----------------
__global__ void prep_kernel(const unsigned int* __restrict__ w) {
    int i = blockIdx.x * blockDim.x + threadIdx.x;
    if (i < N_NODES) g_cursor[i] = 0;
    if (i == 0) {
        int is64 = 1;
        for (int k = 0; k < 64; k++)
            if (w[2 * k + 1] != 0u) { is64 = 0; break; }
        g_is64 = is64;
    }
}

__device__ __forceinline__ int edge_src(const void* ei, int E, int e) {
    return g_is64 ? (int)((const long long*)ei)[e] : ((const int*)ei)[e];
}
__device__ __forceinline__ int edge_dst(const void* ei, int E, int e) {
    return g_is64 ? (int)((const long long*)ei)[E + e] : ((const int*)ei)[E + e];
}

// ---------------- bucket fill (single edge sweep; atomic = reservation + count) ----------------
__global__ void fill_kernel(const void* __restrict__ ei, int E) {
    int e = blockIdx.x * blockDim.x + threadIdx.x;
    if (e >= E) return;
    int s = edge_src(ei, E, e);
    int d = edge_dst(ei, E, e);
    int pos = atomicAdd(&g_cursor[d], 1);
    if (pos < CAP) g_slot[d * CAP + pos] = s;
}

// ---------------- dinv from final counts ----------------
__global__ void dinv_kernel() {
    int i = blockIdx.x * blockDim.x + threadIdx.x;
    if (i < N_NODES) g_dinv[i] = rsqrtf((float)(1 + g_cursor[i]));  // +1 self loop
}

// ---------------- GEMM: hs = (relu?(in) @ W) * dinv, fp16 out ----------------
// 256 threads = 16 row-groups (5 rows each) x 16 col-groups (4 cols each).
template <bool RELU_IN>
__global__ void __launch_bounds__(256) gemm_kernel(
    const float* __restrict__ in, const float* __restrict__ W,
    __half2* __restrict__ hs)
{
    __shared__ float4 Ws[DIM * 16];          // 16KB: W[k][c4] as float4
    __shared__ float  xs[ROWS_PB * DIM];     // 20KB: input tile

    const int tid  = threadIdx.x;
    const int row0 = blockIdx.x * ROWS_PB;

    // Load W (1024 float4) — 4 per thread
    const float4* Wg = (const float4*)W;
    #pragma unroll
    for (int i = 0; i < 4; i++)
        Ws[tid + i * 256] = Wg[tid + i * 256];

    // Load input tile (1280 float4) — 5 per thread, optional ReLU
    #pragma unroll
    for (int j = 0; j < 5; j++) {
        float4 v = ((const float4*)(in + row0 * DIM))[tid + j * 256];
        if (RELU_IN) {
            v.x = fmaxf(v.x, 0.0f); v.y = fmaxf(v.y, 0.0f);
            v.z = fmaxf(v.z, 0.0f); v.w = fmaxf(v.w, 0.0f);
        }
        ((float4*)xs)[tid + j * 256] = v;
    }
    __syncthreads();

    const int rg = tid >> 4;          // row group 0..15
    const int c4 = tid & 15;          // col group 0..15
    const int r0 = rg * RPT;          // first local row

    unsigned long long a01[RPT], a23[RPT];
    #pragma unroll
    for (int j = 0; j < RPT; j++) { a01[j] = 0ull; a23[j] = 0ull; }

    #pragma unroll 4
    for (int k = 0; k < DIM; k += 2) {
        float4 w0 = Ws[k * 16 + c4];
        float4 w1 = Ws[(k + 1) * 16 + c4];
        unsigned long long w0a = pack2(w0.x, w0.y);
        unsigned long long w0b = pack2(w0.z, w0.w);
        unsigned long long w1a = pack2(w1.x, w1.y);
        unsigned long long w1b = pack2(w1.z, w1.w);
        #pragma unroll
        for (int j = 0; j < RPT; j++) {
            float2 xv = *(const float2*)&xs[(r0 + j) * DIM + k];   // LDS.64, two k
            unsigned long long xp0 = pack2(xv.x, xv.x);
            unsigned long long xp1 = pack2(xv.y, xv.y);
            ffma2(a01[j], xp0, w0a);
            ffma2(a23[j], xp0, w0b);
            ffma2(a01[j], xp1, w1a);
            ffma2(a23[j], xp1, w1b);
        }
    }

    // Epilogue: scale by dinv[row], convert to fp16, store 8B per thread
    #pragma unroll
    for (int j = 0; j < RPT; j++) {
        int row = row0 + r0 + j;
        float di = g_dinv[row];
        float2 lo = unpack2(a01[j]);
        float2 hi = unpack2(a23[j]);
        __half2 h0 = __floats2half2_rn(lo.x * di, lo.y * di);
        __half2 h1 = __floats2half2_rn(hi.x * di, hi.y * di);
        unsigned int u0 = *(unsigned int*)&h0;
        unsigned int u1 = *(unsigned int*)&h1;
        ((uint2*)(hs + row * 32))[c4] = make_uint2(u0, u1);
    }
}

// ---------------- bucket gather: out[d] = b + dinv[d] * (hs[d] + sum_in hs[s]) ----------------
// Norm fully pre-scaled into hs: inner loop = pure load+convert+add.
// One warp per destination node; each lane owns 2 columns (one half2).
__global__ void __launch_bounds__(256) gather_kernel(
    const __half2* __restrict__ hs, const float* __restrict__ b,
    float* __restrict__ out)
{
    int node = blockIdx.x * 8 + (threadIdx.x >> 5);
    int lane = threadIdx.x & 31;
    if (node >= N_NODES) return;

    const int* slots = g_slot + node * CAP;
    int cnt = min(g_cursor[node], CAP);

    // self term (hs[node] = h*dinv, so dinv^2*h = dinv*hs — same factored form)
    float2 a0 = __half22float2(hs[node * 32 + lane]);
    float2 a1 = make_float2(0.f, 0.f);
    float2 a2 = make_float2(0.f, 0.f);
    float2 a3 = make_float2(0.f, 0.f);

    int i = 0;
    for (; i + 7 < cnt; i += 8) {
        int4 sA = *(const int4*)(slots + i);        // LDG.128: 4 slot indices
        int4 sB = *(const int4*)(slots + i + 4);    // LDG.128: 4 more
        float2 v0 = __half22float2(hs[sA.x * 32 + lane]);
        float2 v1 = __half22float2(hs[sA.y * 32 + lane]);
        float2 v2 = __half22float2(hs[sA.z * 32 + lane]);
        float2 v3 = __half22float2(hs[sA.w * 32 + lane]);
        float2 v4 = __half22float2(hs[sB.x * 32 + lane]);
        float2 v5 = __half22float2(hs[sB.y * 32 + lane]);
        float2 v6 = __half22float2(hs[sB.z * 32 + lane]);
        float2 v7 = __half22float2(hs[sB.w * 32 + lane]);
        a0.x += v0.x; a0.y += v0.y;
        a1.x += v1.x; a1.y += v1.y;
        a2.x += v2.x; a2.y += v2.y;
        a3.x += v3.x; a3.y += v3.y;
        a0.x += v4.x; a0.y += v4.y;
        a1.x += v5.x; a1.y += v5.y;
        a2.x += v6.x; a2.y += v6.y;
        a3.x += v7.x; a3.y += v7.y;
    }
    if (i + 3 < cnt) {
        int4 sA = *(const int4*)(slots + i);
        float2 v0 = __half22float2(hs[sA.x * 32 + lane]);
        float2 v1 = __half22float2(hs[sA.y * 32 + lane]);
        float2 v2 = __half22float2(hs[sA.z * 32 + lane]);
        float2 v3 = __half22float2(hs[sA.w * 32 + lane]);
        a0.x += v0.x; a0.y += v0.y;
        a1.x += v1.x; a1.y += v1.y;
        a2.x += v2.x; a2.y += v2.y;
        a3.x += v3.x; a3.y += v3.y;
        i += 4;
    }
    for (; i < cnt; i++) {
        float2 v = __half22float2(hs[slots[i] * 32 + lane]);
        a0.x += v.x; a0.y += v.y;
    }

    float2 acc;
    acc.x = (a0.x + a1.x) + (a2.x + a3.x);
    acc.y = (a0.y + a1.y) + (a2.y + a3.y);

    float did = g_dinv[node];
    float2 bv = ((const float2*)b)[lane];
    float2 r;
    r.x = fmaf(acc.x, did, bv.x);
    r.y = fmaf(acc.y, did, bv.y);
    ((float2*)out)[node * 32 + lane] = r;
}

// ---------------- launch ----------------
extern "C" void kernel_launch(void* const* d_in, const int* in_sizes, int n_in,
                              void* d_out, int out_size)
{
    const float* x  = (const float*)d_in[0];
    const void*  ei = d_in[1];
    const float* W0 = (const float*)d_in[2];
    const float* b0 = (const float*)d_in[3];
    const float* W1 = (const float*)d_in[4];
    const float* b1 = (const float*)d_in[5];
    const float* W2 = (const float*)d_in[6];
    const float* b2 = (const float*)d_in[7];
    float* out = (float*)d_out;

    const int E = in_sizes[1] / 2;

    __half2* p_hs;
    float*   p_agg;
    cudaGetSymbolAddress((void**)&p_hs,  g_hs);
    cudaGetSymbolAddress((void**)&p_agg, g_agg);

    const int nodeBlocks = (N_NODES + 255) / 256;
    const int edgeBlocks = (E + 255) / 256;
    const int gemmBlocks = N_NODES / ROWS_PB;          // 625
    const int gathBlocks = (N_NODES + 7) / 8;          // 6250

    // bucket-CSR build (single edge sweep)
    prep_kernel<<<nodeBlocks, 256>>>((const unsigned int*)ei);
    fill_kernel<<<edgeBlocks, 256>>>(ei, E);
    dinv_kernel<<<nodeBlocks, 256>>>();

    // layer 1
    gemm_kernel<false><<<gemmBlocks, 256>>>(x, W0, p_hs);
    gather_kernel<<<gathBlocks, 256>>>(p_hs, b0, p_agg);

    // layer 2
    gemm_kernel<true><<<gemmBlocks, 256>>>(p_agg, W1, p_hs);
    gather_kernel<<<gathBlocks, 256>>>(p_hs, b1, p_agg);

    // layer 3 -> d_out
    gemm_kernel<true><<<gemmBlocks, 256>>>(p_agg, W2, p_hs);
    gather_kernel<<<gathBlocks, 256>>>(p_hs, b2, out);
}